// round 10
// baseline (speedup 1.0000x reference)
#include <cuda_runtime.h>

#define BATCH 32
#define NBOX 300
#define HH 1024
#define WW 1024
#define NTOT (BATCH * NBOX)            /* 9600 */
#define RPB 8                          /* rows per iteration, one per warp */
#define GITER 8                        /* iterations per block */
#define BAND (RPB * GITER)             /* 64 rows per block */
#define CGROUPS (HH / BAND)            /* 16 -> grid 16x32 = 512 blocks */
#define NT 256
#define NBLK (CGROUPS * BATCH)         /* 512 */
#define SCALE 1048576.0f               /* 2^20 fixed-point scale */
#define INV_SCALE (1.0f / 1048576.0f)

// Deterministic integer accumulators (device globals are zero-initialized;
// the tail resets them after each execution for graph replay).
__device__ unsigned long long g_boxsum[NTOT];   // 76 KB
__device__ int g_ctr = 0;

// trunc-toward-zero + clamp, exactly matching the reference
__device__ __forceinline__ int4 box_meta(const float4 bb) {
    int x1 = (int)((bb.x - 0.5f * bb.z) * (float)WW);
    int x2 = (int)((bb.x + 0.5f * bb.z) * (float)WW);
    int y1 = (int)((bb.y - 0.5f * bb.w) * (float)HH);
    int y2 = (int)((bb.y + 0.5f * bb.w) * (float)HH);
    x1 = min(max(x1, 0), WW - 1);
    x2 = min(max(x2, 0), WW - 1);
    y1 = min(max(y1, 0), HH - 1);
    y2 = min(max(y2, 0), HH - 1);
    return make_int4(x1, x2, y1, y2);
}

// ---------------------------------------------------------------------------
// Single kernel. Phase A = round-3 streaming core (best measured: ~41 us).
// Epilogue: scaled-int64 atomicAdd per box (order-independent => deterministic),
// then the globally-last block computes the final scalar.
// ---------------------------------------------------------------------------
__global__ __launch_bounds__(NT, 2)
void main_kernel(const float* __restrict__ seg,
                 const float* __restrict__ boxes,
                 const float* __restrict__ conf,
                 float* __restrict__ out) {
    __shared__ __align__(16) float P[RPB][WW];   // 32 KB exclusive row prefixes

    const int t    = threadIdx.x;
    const int lane = t & 31;
    const int wid  = t >> 5;
    const int b    = blockIdx.y;
    const int Y0   = blockIdx.x * BAND;
    const int base = b * NBOX;

    const float4* __restrict__ bp = (const float4*)boxes;
    int4 bx0 = box_meta(bp[base + t]);                    // t < 256 < 300
    int4 bx1 = (t + NT < NBOX) ? box_meta(bp[base + t + NT])
                               : make_int4(0, 0, 0, 0);

    const float* segD = seg + (size_t)(b * 3 + 1) * HH * WW;
    const float* segF = seg + (size_t)(b * 3 + 2) * HH * WW;

    float4 dv[8], fv[8];
    {   // preload iteration 0
        const float4* dr = (const float4*)(segD + (size_t)(Y0 + wid) * WW);
        const float4* fr = (const float4*)(segF + (size_t)(Y0 + wid) * WW);
        #pragma unroll
        for (int i = 0; i < 8; ++i) {
            dv[i] = __ldcs(&dr[i * 32 + lane]);
            fv[i] = __ldcs(&fr[i * 32 + lane]);
        }
    }

    float a0 = 0.0f, a1 = 0.0f;

    for (int g = 0; g < GITER; ++g) {
        // ---- scan: row -> exclusive prefix in P[wid] (warp-local) ----
        float carry = 0.0f;
        #pragma unroll
        for (int i = 0; i < 8; ++i) {
            float e0 = fv[i].x - dv[i].x;
            float e1 = fv[i].y - dv[i].y;
            float e2 = fv[i].z - dv[i].z;
            float e3 = fv[i].w - dv[i].w;
            float s0 = e0, s1 = s0 + e1, s2 = s1 + e2, s3 = s2 + e3;

            float v = s3;
            #pragma unroll
            for (int o = 1; o < 32; o <<= 1) {
                float n = __shfl_up_sync(0xffffffffu, v, o);
                if (lane >= o) v += n;
            }
            float ex = carry + (v - s3);
            carry += __shfl_sync(0xffffffffu, v, 31);
            *(float4*)&P[wid][i * 128 + lane * 4] =
                make_float4(ex, ex + s0, ex + s1, ex + s2);
        }
        __syncthreads();

        // ---- issue next band's loads (in flight during gather) ----
        if (g + 1 < GITER) {
            const int yn = Y0 + (g + 1) * RPB + wid;
            const float4* dr = (const float4*)(segD + (size_t)yn * WW);
            const float4* fr = (const float4*)(segF + (size_t)yn * WW);
            #pragma unroll
            for (int i = 0; i < 8; ++i) {
                dv[i] = __ldcs(&dr[i * 32 + lane]);
                fv[i] = __ldcs(&fr[i * 32 + lane]);
            }
        }

        // ---- gather: box row-sums from P ----
        const int yb = Y0 + g * RPB;
        #pragma unroll
        for (int r = 0; r < RPB; ++r) {
            const int yy = yb + r;
            if (yy >= bx0.z && yy < bx0.w) a0 += P[r][bx0.y] - P[r][bx0.x];
            if (yy >= bx1.z && yy < bx1.w) a1 += P[r][bx1.y] - P[r][bx1.x];
        }
        __syncthreads();
    }

    // ---- epilogue: deterministic scaled-int64 accumulation ----
    // |a| <= 64*1024 => |a*SCALE| < 2^37; 16 contributions => < 2^41. Safe.
    atomicAdd(&g_boxsum[base + t], (unsigned long long)__float2ll_rn(a0 * SCALE));
    if (t + NT < NBOX)
        atomicAdd(&g_boxsum[base + t + NT],
                  (unsigned long long)__float2ll_rn(a1 * SCALE));

    // ---- last block computes the final scalar ----
    __shared__ int amLast;
    __threadfence();
    if (t == 0) amLast = (atomicAdd(&g_ctr, 1) == NBLK - 1);
    __syncthreads();
    if (!amLast) return;
    __threadfence();

    float val = 0.0f;
    #pragma unroll 4
    for (int j = t; j < NTOT; j += NT) {
        long long sll = (long long)__ldcg(&g_boxsum[j]);
        g_boxsum[j] = 0ull;                         // reset for next replay
        float s = (float)sll * INV_SCALE;
        float4 bb = bp[j];
        int4 m = box_meta(bb);
        float cf = __ldcg(&conf[j]);
        bool valid = (cf >= 0.3f) && (m.y > m.x) && (m.w > m.z);
        float area = (float)((m.w - m.z) * (m.y - m.x));
        val += valid ? fmaxf(s, 0.0f) * (cf / area) : 0.0f;
    }

    // Block reduction (fixed order -> deterministic)
    __shared__ float red[NT / 32];
    #pragma unroll
    for (int o = 16; o; o >>= 1) val += __shfl_down_sync(0xffffffffu, val, o);
    if (lane == 0) red[wid] = val;
    __syncthreads();
    if (t < 32) {
        float v = (t < NT / 32) ? red[t] : 0.0f;
        #pragma unroll
        for (int o = 4; o; o >>= 1) v += __shfl_down_sync(0xffffffffu, v, o);
        if (t == 0) {
            out[0] = v / (float)NTOT;
            g_ctr = 0;                              // reset for next replay
        }
    }
}

extern "C" void kernel_launch(void* const* d_in, const int* in_sizes, int n_in,
                              void* d_out, int out_size) {
    const float* boxes = (const float*)d_in[0];  // (32,300,4)
    const float* conf  = (const float*)d_in[1];  // (32,300)
    const float* seg   = (const float*)d_in[2];  // (32,3,1024,1024)

    dim3 grid(CGROUPS, BATCH);
    main_kernel<<<grid, NT>>>(seg, boxes, conf, (float*)d_out);
}

// round 11
// speedup vs baseline: 1.2917x; 1.2917x over previous
#include <cuda_runtime.h>

#define BATCH 32
#define NBOX 300
#define HH 1024
#define WW 1024
#define NTOT (BATCH * NBOX)            /* 9600 */
#define RPB 8                          /* rows per iteration, one per warp */
#define GITER 8                        /* iterations per block */
#define BAND (RPB * GITER)             /* 64 rows per block */
#define CGROUPS (HH / BAND)            /* 16 -> grid 16x32 = 512 blocks */
#define NT 256
#define RED_BLOCKS ((NTOT + NT - 1) / NT)  /* 38 */

// Scratch (allocation-free device globals). Layout: [chunk][box] (coalesced).
__device__ float g_partial[CGROUPS * NTOT];  // 614 KB
__device__ float g_blk[RED_BLOCKS];
__device__ int   g_ctr = 0;

// trunc-toward-zero + clamp, exactly matching the reference
__device__ __forceinline__ int4 box_meta(const float4 bb) {
    int x1 = (int)((bb.x - 0.5f * bb.z) * (float)WW);
    int x2 = (int)((bb.x + 0.5f * bb.z) * (float)WW);
    int y1 = (int)((bb.y - 0.5f * bb.w) * (float)HH);
    int y2 = (int)((bb.y + 0.5f * bb.w) * (float)HH);
    x1 = min(max(x1, 0), WW - 1);
    x2 = min(max(x2, 0), WW - 1);
    y1 = min(max(y1, 0), HH - 1);
    y2 = min(max(y2, 0), HH - 1);
    return make_int4(x1, x2, y1, y2);
}

// ---------------------------------------------------------------------------
// Main kernel (round-3 proven config, verbatim core): band of 64 rows per
// block, warp-per-row scan, deep register prefetch, occ 2.
// grid = (16, 32) = 512 blocks, block = 256.
// ---------------------------------------------------------------------------
__global__ __launch_bounds__(NT, 2)
void main_kernel(const float* __restrict__ seg, const float* __restrict__ boxes) {
    __shared__ __align__(16) float P[RPB][WW];   // 32 KB exclusive row prefixes

    const int t    = threadIdx.x;
    const int lane = t & 31;
    const int wid  = t >> 5;
    const int b    = blockIdx.y;
    const int Y0   = blockIdx.x * BAND;
    const int base = b * NBOX;

    const float4* __restrict__ bp = (const float4*)boxes;
    int4 bx0 = box_meta(bp[base + t]);                    // t < 256 < 300
    int4 bx1 = (t + NT < NBOX) ? box_meta(bp[base + t + NT])
                               : make_int4(0, 0, 0, 0);

    const float* segD = seg + (size_t)(b * 3 + 1) * HH * WW;
    const float* segF = seg + (size_t)(b * 3 + 2) * HH * WW;

    float4 dv[8], fv[8];
    {   // preload iteration 0
        const float4* dr = (const float4*)(segD + (size_t)(Y0 + wid) * WW);
        const float4* fr = (const float4*)(segF + (size_t)(Y0 + wid) * WW);
        #pragma unroll
        for (int i = 0; i < 8; ++i) {
            dv[i] = __ldcs(&dr[i * 32 + lane]);
            fv[i] = __ldcs(&fr[i * 32 + lane]);
        }
    }

    float a0 = 0.0f, a1 = 0.0f;

    for (int g = 0; g < GITER; ++g) {
        // ---- scan: row -> exclusive prefix in P[wid] (warp-local) ----
        float carry = 0.0f;
        #pragma unroll
        for (int i = 0; i < 8; ++i) {
            float e0 = fv[i].x - dv[i].x;
            float e1 = fv[i].y - dv[i].y;
            float e2 = fv[i].z - dv[i].z;
            float e3 = fv[i].w - dv[i].w;
            float s0 = e0, s1 = s0 + e1, s2 = s1 + e2, s3 = s2 + e3;

            float v = s3;
            #pragma unroll
            for (int o = 1; o < 32; o <<= 1) {
                float n = __shfl_up_sync(0xffffffffu, v, o);
                if (lane >= o) v += n;
            }
            float ex = carry + (v - s3);
            carry += __shfl_sync(0xffffffffu, v, 31);
            *(float4*)&P[wid][i * 128 + lane * 4] =
                make_float4(ex, ex + s0, ex + s1, ex + s2);
        }
        __syncthreads();

        // ---- issue next band's loads (in flight during gather) ----
        if (g + 1 < GITER) {
            const int yn = Y0 + (g + 1) * RPB + wid;
            const float4* dr = (const float4*)(segD + (size_t)yn * WW);
            const float4* fr = (const float4*)(segF + (size_t)yn * WW);
            #pragma unroll
            for (int i = 0; i < 8; ++i) {
                dv[i] = __ldcs(&dr[i * 32 + lane]);
                fv[i] = __ldcs(&fr[i * 32 + lane]);
            }
        }

        // ---- gather: box row-sums from P ----
        const int yb = Y0 + g * RPB;
        #pragma unroll
        for (int r = 0; r < RPB; ++r) {
            const int yy = yb + r;
            if (yy >= bx0.z && yy < bx0.w) a0 += P[r][bx0.y] - P[r][bx0.x];
            if (yy >= bx1.z && yy < bx1.w) a1 += P[r][bx1.y] - P[r][bx1.x];
        }
        __syncthreads();
    }

    g_partial[blockIdx.x * NTOT + base + t] = a0;
    if (t + NT < NBOX) g_partial[blockIdx.x * NTOT + base + t + NT] = a1;

    // PDL: admit the dependent reduce's post-sync phase during our drain.
    cudaTriggerProgrammaticLaunchCompletion();
}

// ---------------------------------------------------------------------------
// Reduction (PDL secondary). All input-independent work happens BEFORE the
// grid dependency sync so it overlaps main's execution; only the g_partial
// reads wait. Deterministic fixed-order reductions throughout.
// ---------------------------------------------------------------------------
__global__ __launch_bounds__(NT)
void reduce_kernel(const float* __restrict__ boxes,
                   const float* __restrict__ conf,
                   float* __restrict__ out) {
    const int t = threadIdx.x;
    const int i = blockIdx.x * NT + t;

    // ---- pre-sync phase: independent of main's output ----
    float w = 0.0f;
    if (i < NTOT) {
        float4 bb = ((const float4*)boxes)[i];
        int4 m = box_meta(bb);
        float cf = conf[i];
        bool valid = (cf >= 0.3f) && (m.y > m.x) && (m.w > m.z);
        float area = (float)((m.w - m.z) * (m.y - m.x));
        w = valid ? (cf / area) : 0.0f;
    }

    cudaGridDependencySynchronize();             // main's partial writes visible

    // ---- post-sync phase: sum partials, weight, reduce ----
    float val = 0.0f;
    if (i < NTOT) {
        float s = 0.0f;
        #pragma unroll
        for (int c = 0; c < CGROUPS; ++c)
            s += g_partial[c * NTOT + i];
        val = fmaxf(s, 0.0f) * w;
    }

    __shared__ float red[NT / 32];
    #pragma unroll
    for (int o = 16; o; o >>= 1) val += __shfl_down_sync(0xffffffffu, val, o);
    if ((t & 31) == 0) red[t >> 5] = val;
    __syncthreads();
    if (t < 32) {
        float v = (t < NT / 32) ? red[t] : 0.0f;
        #pragma unroll
        for (int o = 4; o; o >>= 1) v += __shfl_down_sync(0xffffffffu, v, o);
        if (t == 0) g_blk[blockIdx.x] = v;
    }

    __shared__ int amLast;
    __threadfence();
    if (t == 0) amLast = (atomicAdd(&g_ctr, 1) == gridDim.x - 1);
    __syncthreads();
    if (amLast) {
        __threadfence();
        if (t < 32) {
            float v = g_blk[t];                       // t < 32 < 38
            if (t + 32 < RED_BLOCKS) v += g_blk[t + 32];
            #pragma unroll
            for (int o = 16; o; o >>= 1) v += __shfl_down_sync(0xffffffffu, v, o);
            if (t == 0) {
                out[0] = v / (float)NTOT;
                g_ctr = 0;                            // reset for next replay
            }
        }
    }
}

extern "C" void kernel_launch(void* const* d_in, const int* in_sizes, int n_in,
                              void* d_out, int out_size) {
    const float* boxes = (const float*)d_in[0];  // (32,300,4)
    const float* conf  = (const float*)d_in[1];  // (32,300)
    const float* seg   = (const float*)d_in[2];  // (32,3,1024,1024)

    dim3 grid(CGROUPS, BATCH);
    main_kernel<<<grid, NT>>>(seg, boxes);

    // PDL: overlap reduce's launch/ramp + pre-sync phase with main.
    cudaLaunchConfig_t cfg = {};
    cfg.gridDim  = dim3(RED_BLOCKS, 1, 1);
    cfg.blockDim = dim3(NT, 1, 1);
    cfg.dynamicSmemBytes = 0;
    cfg.stream = 0;
    cudaLaunchAttribute attr[1];
    attr[0].id = cudaLaunchAttributeProgrammaticStreamSerialization;
    attr[0].val.programmaticStreamSerializationAllowed = 1;
    cfg.attrs = attr;
    cfg.numAttrs = 1;
    cudaLaunchKernelEx(&cfg, reduce_kernel, boxes, conf, (float*)d_out);
}